// round 16
// baseline (speedup 1.0000x reference)
#include <cuda_runtime.h>
#include <cuda_fp16.h>
#include <math.h>
#include <stdint.h>

// Problem constants
#define Bq 4
#define Sq 4096
#define Dq 1024
#define Mq (Bq * Sq)          // 16384 rows
#define CHUNKq 64
#define NCHUNK (Sq / CHUNKq)  // 64

// ---------------------------------------------------------------------------
// PTX helpers (compute_103-safe)
// ---------------------------------------------------------------------------
__device__ __forceinline__ uint32_t smem_u32(const void* p) {
    uint32_t a;
    asm("{ .reg .u64 t; cvta.to.shared.u64 t, %1; cvt.u32.u64 %0, t; }" : "=r"(a) : "l"(p));
    return a;
}
#define CP_ASYNC16(dst, src) \
    asm volatile("cp.async.cg.shared.global [%0], [%1], 16;" :: "r"(dst), "l"(src))
#define CP_COMMIT() asm volatile("cp.async.commit_group;" ::: "memory")
#define CP_WAIT1()  asm volatile("cp.async.wait_group 1;" ::: "memory")

__device__ __forceinline__ void ldsm4(uint32_t* r, uint32_t addr) {
    asm volatile("ldmatrix.sync.aligned.m8n8.x4.shared.b16 {%0,%1,%2,%3}, [%4];"
                 : "=r"(r[0]), "=r"(r[1]), "=r"(r[2]), "=r"(r[3]) : "r"(addr));
}
__device__ __forceinline__ void mma_f16(float* d, const uint32_t* a, uint32_t b0, uint32_t b1) {
    asm volatile(
        "mma.sync.aligned.m16n8k16.row.col.f32.f16.f16.f32 "
        "{%0,%1,%2,%3}, {%4,%5,%6,%7}, {%8,%9}, {%0,%1,%2,%3};"
        : "+f"(d[0]), "+f"(d[1]), "+f"(d[2]), "+f"(d[3])
        : "r"(a[0]), "r"(a[1]), "r"(a[2]), "r"(a[3]), "r"(b0), "r"(b1));
}

// Fast tanh: Pade(7,6). rel err <1e-7 for |x|<3, clamped beyond.
__device__ __forceinline__ float ftanh(float x) {
    const float s = x * x;
    const float num = x * fmaf(s, fmaf(s, (s + 378.0f), 17325.0f), 135135.0f);
    const float den = fmaf(s, fmaf(s, fmaf(s, 28.0f, 3150.0f), 62370.0f), 135135.0f);
    float r;
    asm("rcp.approx.f32 %0, %1;" : "=f"(r) : "f"(den));
    return fminf(fmaxf(num * r, -1.0f), 1.0f);
}
__device__ __forceinline__ float fsin(float x) { float r; asm("sin.approx.f32 %0, %1;" : "=f"(r) : "f"(x)); return r; }
__device__ __forceinline__ float fcos(float x) { float r; asm("cos.approx.f32 %0, %1;" : "=f"(r) : "f"(x)); return r; }

// ---------------------------------------------------------------------------
// Scratch (device globals — allocation-free per harness rules)
// ---------------------------------------------------------------------------
__device__ __align__(256) __half g_xh[(size_t)Mq * Dq];   // x fp16, later: retrieved fp16
__device__ __align__(256) __half g_vh[(size_t)Mq * Dq];   // value fp16
__device__ __align__(256) __half g_kh[(size_t)Mq * Dq];   // kp_lin fp16
__device__ __align__(256) __half g_qh[(size_t)Mq * Dq];   // qp_lin fp16
__device__ __align__(256) __half g_ah[(size_t)Mq * Dq];   // ln output fp16
__device__ __align__(256) __half g_wh[8 * (size_t)Dq * Dq];
// slots: 0=Wv64 1=Wo64 2=Wkp64 3=Wqp64 4=WkT64 5=WqT64 6=Ckp64 7=Cqp64
__device__ float g_zero[Dq];
__device__ float g_bkp[Dq];
__device__ float g_bqp[Dq];

// ---------------------------------------------------------------------------
// ONE merged prep kernel, grid (1024, 24)
// ---------------------------------------------------------------------------
__global__ __launch_bounds__(256)
void prep_kernel(const float* __restrict__ x, __half* __restrict__ xh,
                 const float* __restrict__ Wv, const float* __restrict__ Wo,
                 const float* __restrict__ Wkp, const float* __restrict__ Wqp,
                 __half* __restrict__ whV, __half* __restrict__ whO,
                 __half* __restrict__ whKP, __half* __restrict__ whQP,
                 const float* __restrict__ Wk, __half* __restrict__ whKT,
                 const float* __restrict__ Wq, __half* __restrict__ whQT,
                 const float* __restrict__ bk, const float* __restrict__ bkp, float* __restrict__ bkpc,
                 const float* __restrict__ bq, const float* __restrict__ bqp, float* __restrict__ bqpc)
{
    __shared__ float tile[32][33];
    const int sec = blockIdx.y;
    const int bx  = blockIdx.x;
    const int tid = threadIdx.x;

    if (sec < 16) {
        const size_t i4 = ((size_t)sec * 1024 + bx) * 256 + tid;
        float4 v = *(const float4*)(x + i4 * 4);
        __half2 a = __floats2half2_rn(v.x, v.y);
        __half2 b = __floats2half2_rn(v.z, v.w);
        uint2 p; p.x = *(uint32_t*)&a; p.y = *(uint32_t*)&b;
        *(uint2*)(xh + i4 * 4) = p;
    } else if (sec < 20) {
        const float* in;
        __half* out;
        switch (sec - 16) {
            case 0: in = Wv;  out = whV;  break;
            case 1: in = Wo;  out = whO;  break;
            case 2: in = Wkp; out = whKP; break;
            default: in = Wqp; out = whQP; break;
        }
        const size_t i4 = (size_t)bx * 256 + tid;
        float4 v = *(const float4*)(in + i4 * 4);
        __half2 a = __floats2half2_rn(v.x * 64.0f, v.y * 64.0f);
        __half2 b = __floats2half2_rn(v.z * 64.0f, v.w * 64.0f);
        uint2 p; p.x = *(uint32_t*)&a; p.y = *(uint32_t*)&b;
        *(uint2*)(out + i4 * 4) = p;
    } else if (sec < 22) {
        const float* in = (sec == 21) ? Wq : Wk;
        __half* out = (sec == 21) ? whQT : whKT;
        const int x0 = (bx & 31) * 32;
        const int y0 = (bx >> 5) * 32;
        const int tx = tid & 31;
        const int ty = tid >> 5;
#pragma unroll
        for (int i = 0; i < 32; i += 8)
            tile[ty + i][tx] = in[(size_t)(y0 + ty + i) * Dq + x0 + tx];
        __syncthreads();
#pragma unroll
        for (int i = 0; i < 32; i += 8)
            out[(size_t)(x0 + ty + i) * Dq + y0 + tx] = __float2half_rn(tile[tx][ty + i] * 64.0f);
    } else {
        const float* W  = (sec == 23) ? Wqp : Wkp;
        const float* v  = (sec == 23) ? bq  : bk;
        const float* b2 = (sec == 23) ? bqp : bkp;
        float* out = (sec == 23) ? bqpc : bkpc;
        const int row = bx;
        float4 a = ((const float4*)(W + (size_t)row * Dq))[tid];
        float4 xv = ((const float4*)v)[tid];
        float s = a.x * xv.x + a.y * xv.y + a.z * xv.z + a.w * xv.w;
#pragma unroll
        for (int o = 16; o > 0; o >>= 1) s += __shfl_xor_sync(0xFFFFFFFFu, s, o);
        if ((tid & 31) == 0) tile[0][tid >> 5] = s;
        __syncthreads();
        if (tid == 0) {
            float t = tile[0][0] + tile[0][1] + tile[0][2] + tile[0][3]
                    + tile[0][4] + tile[0][5] + tile[0][6] + tile[0][7];
            out[row] = t + b2[row];
        }
    }
}

// ---------------------------------------------------------------------------
// fp16 single-product GEMM (NT): C = (A * W64) / 64 + bias (+resid)
// R12 config (hardware floor: fp32-acc HMMA rt_SMSP=16):
// CTA 128x128, 8 warps of 32x64 tiles, K-step 64, 3-stage, 2 CTAs/SM.
// ---------------------------------------------------------------------------
constexpr int ROW_B    = 144;               // 64 halves (128B) + 16B pad
constexpr int TILE_B   = 128 * ROW_B;       // 18432
constexpr int STAGE_B  = 2 * TILE_B;        // 36864 (A | W)
constexpr int SMEM_TOT = 3 * STAGE_B;       // 110592
#define GEMM_THREADS 256

__device__ __forceinline__ void load_stage(
    uint32_t sb_stage, int kb, int tid,
    const __half* __restrict__ A, const __half* __restrict__ W, int bm, int bn)
{
#pragma unroll
    for (int i = 0; i < 8; i++) {
        const int idx = i * 256 + tid;          // 0..2047
        const int t   = idx >> 10;              // 0 = A, 1 = W
        const int row = (idx >> 3) & 127;
        const int ch  = idx & 7;
        const __half* src = (t ? W : A) + (((size_t)((t ? bn : bm) + row)) << 10)
                          + kb * 64 + ch * 8;
        CP_ASYNC16(sb_stage + t * TILE_B + row * ROW_B + ch * 16, src);
    }
}

template <bool OUT_FP16, bool RESID>
__device__ __forceinline__ void gemm_body(
    const __half* __restrict__ A, const __half* __restrict__ W,
    const float* __restrict__ bias, const float* __restrict__ resid,
    float* __restrict__ Cf, __half* __restrict__ Ch, int bm, int bn)
{
    extern __shared__ __align__(128) char smem[];
    const uint32_t sb = smem_u32(smem);
    const int tid  = threadIdx.x;
    const int wid  = tid >> 5;
    const int lane = tid & 31;
    const int wm = (wid >> 1) * 32;   // 0,32,64,96
    const int wn = (wid & 1) * 64;    // 0,64
    const int kstag = (wid >> 2) * 2; // 0 or 2: stagger for SMSP co-residents

    float acc[2][8][4];
#pragma unroll
    for (int i = 0; i < 2; i++)
#pragma unroll
        for (int j = 0; j < 8; j++)
#pragma unroll
            for (int k = 0; k < 4; k++) acc[i][j][k] = 0.0f;

    load_stage(sb + 0 * STAGE_B, 0, tid, A, W, bm, bn); CP_COMMIT();
    load_stage(sb + 1 * STAGE_B, 1, tid, A, W, bm, bn); CP_COMMIT();

    const int sub = lane >> 3;
    const int rr  = lane & 7;
    const int rowsel = (sub & 1) * 8 + rr;
    const int ksel   = (sub >> 1) * 16;

    for (int kb = 0; kb < 16; kb++) {
        CP_WAIT1();
        __syncthreads();
        if (kb + 2 < 16)
            load_stage(sb + ((kb + 2) % 3) * STAGE_B, kb + 2, tid, A, W, bm, bn);
        CP_COMMIT();

        const uint32_t st = sb + (kb % 3) * STAGE_B;
        const uint32_t sA = st;
        const uint32_t sB = st + TILE_B;

#pragma unroll
        for (int kq = 0; kq < 4; kq++) {
            const int kk = (kq + kstag) & 3;
            const int koff = kk * 32 + ksel;
            uint32_t fa[2][4], fb[4][4];
#pragma unroll
            for (int mt = 0; mt < 2; mt++)
                ldsm4(fa[mt], sA + (wm + mt * 16 + rowsel) * ROW_B + koff);
#pragma unroll
            for (int g = 0; g < 4; g++)
                ldsm4(fb[g], sB + (wn + g * 16 + rowsel) * ROW_B + koff);
#pragma unroll
            for (int mt = 0; mt < 2; mt++) {
#pragma unroll
                for (int g = 0; g < 4; g++) {
                    mma_f16(acc[mt][2 * g],     fa[mt], fb[g][0], fb[g][2]);
                    mma_f16(acc[mt][2 * g + 1], fa[mt], fb[g][1], fb[g][3]);
                }
            }
        }
    }

    const int qrow = lane >> 2;
    const int qcol = (lane & 3) * 2;
#pragma unroll
    for (int mt = 0; mt < 2; mt++) {
#pragma unroll
        for (int nt = 0; nt < 8; nt++) {
            const int col = bn + wn + nt * 8 + qcol;
            const float bz0 = __ldg(bias + col);
            const float bz1 = __ldg(bias + col + 1);
#pragma unroll
            for (int h = 0; h < 2; h++) {
                const int row = bm + wm + mt * 16 + h * 8 + qrow;
                float v0 = acc[mt][nt][2 * h + 0] * 0.015625f + bz0;
                float v1 = acc[mt][nt][2 * h + 1] * 0.015625f + bz1;
                const size_t go = ((size_t)row << 10) + col;
                if (RESID) {
                    float2 x2 = *(const float2*)(resid + go);
                    v0 += x2.x; v1 += x2.y;
                }
                if (OUT_FP16) {
                    __half2 hv = __floats2half2_rn(v0, v1);
                    *(uint32_t*)(Ch + go) = *(uint32_t*)&hv;
                } else {
                    float2 o; o.x = v0; o.y = v1;
                    *(float2*)(Cf + go) = o;
                }
            }
        }
    }
}

// value GEMM (1024 tiles) + the two weight-combine GEMMs (128 tiles), one launch.
__global__ __launch_bounds__(GEMM_THREADS, 2)
void gemm_value_combine(
    const __half* __restrict__ xh, const __half* __restrict__ whV,
    const float* __restrict__ bv, __half* __restrict__ vh,
    const __half* __restrict__ whKP, const __half* __restrict__ whKT, __half* __restrict__ whCK,
    const __half* __restrict__ whQP, const __half* __restrict__ whQT, __half* __restrict__ whCQ,
    const float* __restrict__ zerob)
{
    const int by = blockIdx.y;
    const int bn = blockIdx.x * 128;
    if (by < 128) {
        gemm_body<true, false>(xh, whV, bv, nullptr, nullptr, vh, by * 128, bn);
    } else if (by < 136) {
        gemm_body<true, false>(whKP, whKT, zerob, nullptr, nullptr, whCK, (by - 128) * 128, bn);
    } else {
        gemm_body<true, false>(whQP, whQT, zerob, nullptr, nullptr, whCQ, (by - 136) * 128, bn);
    }
}

// kp + qp GEMMs in one launch: grid (8, 128, 2)
__global__ __launch_bounds__(GEMM_THREADS, 2)
void gemm_kq_dual(const __half* __restrict__ xh,
                  const __half* __restrict__ whCK, const float* __restrict__ bkpc, __half* __restrict__ kh,
                  const __half* __restrict__ whCQ, const float* __restrict__ bqpc, __half* __restrict__ qh)
{
    if (blockIdx.z == 0)
        gemm_body<true, false>(xh, whCK, bkpc, nullptr, nullptr, kh, blockIdx.y * 128, blockIdx.x * 128);
    else
        gemm_body<true, false>(xh, whCQ, bqpc, nullptr, nullptr, qh, blockIdx.y * 128, blockIdx.x * 128);
}

// out-projection GEMM with residual, fp32 output
__global__ __launch_bounds__(GEMM_THREADS, 2)
void gemm_out(const __half* __restrict__ A, const __half* __restrict__ W,
              const float* __restrict__ bias, const float* __restrict__ resid,
              float* __restrict__ Cf)
{
    gemm_body<false, true>(A, W, bias, resid, Cf, nullptr, blockIdx.y * 128, blockIdx.x * 128);
}

// ---------------------------------------------------------------------------
// Phasor kernel: no LN, no barriers. Grid 512 blocks (chunk x d-half),
// 256 threads x 2 d each -> all blocks resident in ~1 wave.
// Writes retrieved fp16.
// ---------------------------------------------------------------------------
__global__ __launch_bounds__(256)
void phasor_kernel(const __half* __restrict__ kp16, const __half* __restrict__ qp16,
                   const __half* __restrict__ v16,  const float* __restrict__ ps,
                   __half* __restrict__ rout)
{
    const int chunk = blockIdx.x >> 1;
    const int d0 = ((blockIdx.x & 1) << 9) + threadIdx.x * 2;
    const float2 ps2 = *(const float2*)(ps + d0);
    float mr0 = 0.0f, mi0 = 0.0f, mr1 = 0.0f, mi1 = 0.0f;
    size_t off = ((size_t)chunk * CHUNKq << 10) + d0;

#pragma unroll 4
    for (int s = 0; s < CHUNKq; s++) {
        uint32_t kpu = *(const uint32_t*)(kp16 + off);
        uint32_t qpu = *(const uint32_t*)(qp16 + off);
        uint32_t vu  = *(const uint32_t*)(v16 + off);
        float2 kpf = __half22float2(*(__half2*)&kpu);
        float2 qpf = __half22float2(*(__half2*)&qpu);
        float2 vf  = __half22float2(*(__half2*)&vu);

        const float kpa = ftanh(kpf.x) * ps2.x;
        const float kpb = ftanh(kpf.y) * ps2.y;
        const float qpa = ftanh(qpf.x) * ps2.x;
        const float qpb = ftanh(qpf.y) * ps2.y;
        mr0 = fmaf(vf.x, fcos(kpa), mr0);
        mi0 = fmaf(vf.x, fsin(kpa), mi0);
        mr1 = fmaf(vf.y, fcos(kpb), mr1);
        mi1 = fmaf(vf.y, fsin(kpb), mi1);
        const float r0 = (mr0 * fcos(qpa) + mi0 * fsin(qpa)) * 0.03125f;
        const float r1 = (mr1 * fcos(qpb) + mi1 * fsin(qpb)) * 0.03125f;
        __half2 hv = __floats2half2_rn(r0, r1);
        *(uint32_t*)(rout + off) = *(uint32_t*)&hv;
        off += Dq;
    }
}

// ---------------------------------------------------------------------------
// LayerNorm: one block (128 threads) per row, 8 elems/thread, fp16 in/out.
// ---------------------------------------------------------------------------
__global__ __launch_bounds__(128)
void ln_kernel(const __half* __restrict__ rin, const float* __restrict__ g,
               const float* __restrict__ b, __half* __restrict__ outh)
{
    __shared__ float sred[8];
    const int row = blockIdx.x;
    const int tid = threadIdx.x;
    const int warp = tid >> 5;
    const int lane = tid & 31;
    const size_t base = ((size_t)row << 10) + tid * 8;

    uint4 rv = *(const uint4*)(rin + base);
    float f[8];
    {
        float2 a = __half22float2(*(__half2*)&rv.x);
        float2 c = __half22float2(*(__half2*)&rv.y);
        float2 d = __half22float2(*(__half2*)&rv.z);
        float2 e = __half22float2(*(__half2*)&rv.w);
        f[0] = a.x; f[1] = a.y; f[2] = c.x; f[3] = c.y;
        f[4] = d.x; f[5] = d.y; f[6] = e.x; f[7] = e.y;
    }
    float s1 = 0.0f, s2 = 0.0f;
#pragma unroll
    for (int j = 0; j < 8; j++) { s1 += f[j]; s2 = fmaf(f[j], f[j], s2); }
#pragma unroll
    for (int o = 16; o > 0; o >>= 1) {
        s1 += __shfl_xor_sync(0xFFFFFFFFu, s1, o);
        s2 += __shfl_xor_sync(0xFFFFFFFFu, s2, o);
    }
    if (lane == 0) { sred[warp] = s1; sred[4 + warp] = s2; }
    __syncthreads();
    const float ts1 = sred[0] + sred[1] + sred[2] + sred[3];
    const float ts2 = sred[4] + sred[5] + sred[6] + sred[7];
    const float mu   = ts1 * (1.0f / Dq);
    const float var  = ts2 * (1.0f / Dq) - mu * mu;
    const float rstd = rsqrtf(var + 1e-5f);

    float4 g0 = *(const float4*)(g + tid * 8);
    float4 g1 = *(const float4*)(g + tid * 8 + 4);
    float4 b0 = *(const float4*)(b + tid * 8);
    float4 b1 = *(const float4*)(b + tid * 8 + 4);
    const float gg[8] = {g0.x, g0.y, g0.z, g0.w, g1.x, g1.y, g1.z, g1.w};
    const float bb[8] = {b0.x, b0.y, b0.z, b0.w, b1.x, b1.y, b1.z, b1.w};
    uint4 ov;
    uint32_t* op = (uint32_t*)&ov;
#pragma unroll
    for (int j = 0; j < 4; j++) {
        __half2 hv = __floats2half2_rn((f[2 * j + 0] - mu) * rstd * gg[2 * j + 0] + bb[2 * j + 0],
                                       (f[2 * j + 1] - mu) * rstd * gg[2 * j + 1] + bb[2 * j + 1]);
        op[j] = *(uint32_t*)&hv;
    }
    *(uint4*)(outh + base) = ov;
}

// ---------------------------------------------------------------------------
// Launch
// ---------------------------------------------------------------------------
extern "C" void kernel_launch(void* const* d_in, const int* in_sizes, int n_in,
                              void* d_out, int out_size)
{
    (void)in_sizes; (void)n_in; (void)out_size;
    const float* x   = (const float*)d_in[0];
    const float* Wk  = (const float*)d_in[1];
    const float* bk  = (const float*)d_in[2];
    const float* Wv  = (const float*)d_in[3];
    const float* bv  = (const float*)d_in[4];
    const float* Wq  = (const float*)d_in[5];
    const float* bq  = (const float*)d_in[6];
    const float* Wkp = (const float*)d_in[7];
    const float* bkp = (const float*)d_in[8];
    const float* Wqp = (const float*)d_in[9];
    const float* bqp = (const float*)d_in[10];
    const float* ps  = (const float*)d_in[11];
    const float* lng = (const float*)d_in[12];
    const float* lnb = (const float*)d_in[13];
    const float* Wo  = (const float*)d_in[14];
    const float* bo  = (const float*)d_in[15];
    float* out = (float*)d_out;

    float *zero, *bkpc, *bqpc;
    __half *xh, *vh, *kh, *qh, *ah, *wh;
    cudaGetSymbolAddress((void**)&xh, g_xh);
    cudaGetSymbolAddress((void**)&vh, g_vh);
    cudaGetSymbolAddress((void**)&kh, g_kh);
    cudaGetSymbolAddress((void**)&qh, g_qh);
    cudaGetSymbolAddress((void**)&ah, g_ah);
    cudaGetSymbolAddress((void**)&wh, g_wh);
    cudaGetSymbolAddress((void**)&zero, g_zero);
    cudaGetSymbolAddress((void**)&bkpc, g_bkp);
    cudaGetSymbolAddress((void**)&bqpc, g_bqp);

    cudaFuncSetAttribute(gemm_value_combine, cudaFuncAttributeMaxDynamicSharedMemorySize, SMEM_TOT);
    cudaFuncSetAttribute(gemm_kq_dual,       cudaFuncAttributeMaxDynamicSharedMemorySize, SMEM_TOT);
    cudaFuncSetAttribute(gemm_out,           cudaFuncAttributeMaxDynamicSharedMemorySize, SMEM_TOT);

    const size_t WN = (size_t)Dq * Dq;
    __half* whV  = wh + 0 * WN;
    __half* whO  = wh + 1 * WN;
    __half* whKP = wh + 2 * WN;
    __half* whQP = wh + 3 * WN;
    __half* whKT = wh + 4 * WN;
    __half* whQT = wh + 5 * WN;
    __half* whCK = wh + 6 * WN;
    __half* whCQ = wh + 7 * WN;

    // ONE prep launch: x convert + weight converts + transposes + bias matvecs
    prep_kernel<<<dim3(1024, 24), 256>>>(
        x, xh, Wv, Wo, Wkp, Wqp, whV, whO, whKP, whQP,
        Wk, whKT, Wq, whQT, bk, bkp, bkpc, bq, bqp, bqpc);

    const dim3 block(GEMM_THREADS);
    // value GEMM + weight combines, one launch
    gemm_value_combine<<<dim3(8, 144), block, SMEM_TOT>>>(
        xh, whV, bv, vh, whKP, whKT, whCK, whQP, whQT, whCQ, zero);

    // kp + qp GEMMs, one launch
    gemm_kq_dual<<<dim3(8, 128, 2), block, SMEM_TOT>>>(xh, whCK, bkpc, kh, whCQ, bqpc, qh);

    // Phasor (xh is dead after kq_dual -> reuse as retrieved buffer)
    phasor_kernel<<<Bq * NCHUNK * 2, 256>>>(kh, qh, vh, ps, xh);

    // LayerNorm: retrieved (xh) -> ah fp16
    ln_kernel<<<Mq, 128>>>(xh, lng, lnb, ah);

    // out = x + ln @ Wo + bo
    gemm_out<<<dim3(8, 128), block, SMEM_TOT>>>(ah, whO, bo, x, out);
}

// round 17
// speedup vs baseline: 1.0375x; 1.0375x over previous
#include <cuda_runtime.h>
#include <cuda_fp16.h>
#include <math.h>
#include <stdint.h>

// Problem constants
#define Bq 4
#define Sq 4096
#define Dq 1024
#define Mq (Bq * Sq)          // 16384 rows
#define CHUNKq 64
#define NCHUNK (Sq / CHUNKq)  // 64

// ---------------------------------------------------------------------------
// PTX helpers (compute_103-safe)
// ---------------------------------------------------------------------------
__device__ __forceinline__ uint32_t smem_u32(const void* p) {
    uint32_t a;
    asm("{ .reg .u64 t; cvta.to.shared.u64 t, %1; cvt.u32.u64 %0, t; }" : "=r"(a) : "l"(p));
    return a;
}
#define CP_ASYNC16(dst, src) \
    asm volatile("cp.async.cg.shared.global [%0], [%1], 16;" :: "r"(dst), "l"(src))
#define CP_COMMIT() asm volatile("cp.async.commit_group;" ::: "memory")
#define CP_WAIT1()  asm volatile("cp.async.wait_group 1;" ::: "memory")
#define BAR_SYNC_256(id) asm volatile("bar.sync %0, 256;" :: "r"(id) : "memory")

__device__ __forceinline__ void ldsm4(uint32_t* r, uint32_t addr) {
    asm volatile("ldmatrix.sync.aligned.m8n8.x4.shared.b16 {%0,%1,%2,%3}, [%4];"
                 : "=r"(r[0]), "=r"(r[1]), "=r"(r[2]), "=r"(r[3]) : "r"(addr));
}
__device__ __forceinline__ void mma_f16(float* d, const uint32_t* a, uint32_t b0, uint32_t b1) {
    asm volatile(
        "mma.sync.aligned.m16n8k16.row.col.f32.f16.f16.f32 "
        "{%0,%1,%2,%3}, {%4,%5,%6,%7}, {%8,%9}, {%0,%1,%2,%3};"
        : "+f"(d[0]), "+f"(d[1]), "+f"(d[2]), "+f"(d[3])
        : "r"(a[0]), "r"(a[1]), "r"(a[2]), "r"(a[3]), "r"(b0), "r"(b1));
}

// Fast tanh: Pade(7,6). rel err <1e-7 for |x|<3, clamped beyond.
__device__ __forceinline__ float ftanh(float x) {
    const float s = x * x;
    const float num = x * fmaf(s, fmaf(s, (s + 378.0f), 17325.0f), 135135.0f);
    const float den = fmaf(s, fmaf(s, fmaf(s, 28.0f, 3150.0f), 62370.0f), 135135.0f);
    float r;
    asm("rcp.approx.f32 %0, %1;" : "=f"(r) : "f"(den));
    return fminf(fmaxf(num * r, -1.0f), 1.0f);
}
__device__ __forceinline__ float fsin(float x) { float r; asm("sin.approx.f32 %0, %1;" : "=f"(r) : "f"(x)); return r; }
__device__ __forceinline__ float fcos(float x) { float r; asm("cos.approx.f32 %0, %1;" : "=f"(r) : "f"(x)); return r; }

// ---------------------------------------------------------------------------
// Scratch (device globals — allocation-free per harness rules)
// ---------------------------------------------------------------------------
__device__ __align__(256) __half g_xh[(size_t)Mq * Dq];   // x fp16
__device__ __align__(256) __half g_vh[(size_t)Mq * Dq];   // value fp16
__device__ __align__(256) __half g_kh[(size_t)Mq * Dq];   // kp_lin fp16
__device__ __align__(256) __half g_qh[(size_t)Mq * Dq];   // qp_lin fp16
__device__ __align__(256) __half g_ah[(size_t)Mq * Dq];   // ln output fp16
__device__ __align__(256) __half g_wh[8 * (size_t)Dq * Dq];
// slots: 0=Wv64 1=Wo64 2=Wkp64 3=Wqp64 4=WkT64 5=WqT64 6=Ckp64 7=Cqp64
__device__ float g_zero[Dq];
__device__ float g_bkp[Dq];
__device__ float g_bqp[Dq];

// ---------------------------------------------------------------------------
// ONE merged prep kernel, grid (1024, 24)
// ---------------------------------------------------------------------------
__global__ __launch_bounds__(256)
void prep_kernel(const float* __restrict__ x, __half* __restrict__ xh,
                 const float* __restrict__ Wv, const float* __restrict__ Wo,
                 const float* __restrict__ Wkp, const float* __restrict__ Wqp,
                 __half* __restrict__ whV, __half* __restrict__ whO,
                 __half* __restrict__ whKP, __half* __restrict__ whQP,
                 const float* __restrict__ Wk, __half* __restrict__ whKT,
                 const float* __restrict__ Wq, __half* __restrict__ whQT,
                 const float* __restrict__ bk, const float* __restrict__ bkp, float* __restrict__ bkpc,
                 const float* __restrict__ bq, const float* __restrict__ bqp, float* __restrict__ bqpc)
{
    __shared__ float tile[32][33];
    const int sec = blockIdx.y;
    const int bx  = blockIdx.x;
    const int tid = threadIdx.x;

    if (sec < 16) {
        const size_t i4 = ((size_t)sec * 1024 + bx) * 256 + tid;
        float4 v = *(const float4*)(x + i4 * 4);
        __half2 a = __floats2half2_rn(v.x, v.y);
        __half2 b = __floats2half2_rn(v.z, v.w);
        uint2 p; p.x = *(uint32_t*)&a; p.y = *(uint32_t*)&b;
        *(uint2*)(xh + i4 * 4) = p;
    } else if (sec < 20) {
        const float* in;
        __half* out;
        switch (sec - 16) {
            case 0: in = Wv;  out = whV;  break;
            case 1: in = Wo;  out = whO;  break;
            case 2: in = Wkp; out = whKP; break;
            default: in = Wqp; out = whQP; break;
        }
        const size_t i4 = (size_t)bx * 256 + tid;
        float4 v = *(const float4*)(in + i4 * 4);
        __half2 a = __floats2half2_rn(v.x * 64.0f, v.y * 64.0f);
        __half2 b = __floats2half2_rn(v.z * 64.0f, v.w * 64.0f);
        uint2 p; p.x = *(uint32_t*)&a; p.y = *(uint32_t*)&b;
        *(uint2*)(out + i4 * 4) = p;
    } else if (sec < 22) {
        const float* in = (sec == 21) ? Wq : Wk;
        __half* out = (sec == 21) ? whQT : whKT;
        const int x0 = (bx & 31) * 32;
        const int y0 = (bx >> 5) * 32;
        const int tx = tid & 31;
        const int ty = tid >> 5;
#pragma unroll
        for (int i = 0; i < 32; i += 8)
            tile[ty + i][tx] = in[(size_t)(y0 + ty + i) * Dq + x0 + tx];
        __syncthreads();
#pragma unroll
        for (int i = 0; i < 32; i += 8)
            out[(size_t)(x0 + ty + i) * Dq + y0 + tx] = __float2half_rn(tile[tx][ty + i] * 64.0f);
    } else {
        const float* W  = (sec == 23) ? Wqp : Wkp;
        const float* v  = (sec == 23) ? bq  : bk;
        const float* b2 = (sec == 23) ? bqp : bkp;
        float* out = (sec == 23) ? bqpc : bkpc;
        const int row = bx;
        float4 a = ((const float4*)(W + (size_t)row * Dq))[tid];
        float4 xv = ((const float4*)v)[tid];
        float s = a.x * xv.x + a.y * xv.y + a.z * xv.z + a.w * xv.w;
#pragma unroll
        for (int o = 16; o > 0; o >>= 1) s += __shfl_xor_sync(0xFFFFFFFFu, s, o);
        if ((tid & 31) == 0) tile[0][tid >> 5] = s;
        __syncthreads();
        if (tid == 0) {
            float t = tile[0][0] + tile[0][1] + tile[0][2] + tile[0][3]
                    + tile[0][4] + tile[0][5] + tile[0][6] + tile[0][7];
            out[row] = t + b2[row];
        }
    }
}

// ---------------------------------------------------------------------------
// fp16 single-product GEMM (NT): C = (A * W64) / 64 + bias (+resid)
// R12 config (hardware floor: fp32-acc HMMA rt_SMSP=16):
// CTA 128x128, 8 warps of 32x64 tiles, K-step 64, 3-stage, 2 CTAs/SM.
// ---------------------------------------------------------------------------
constexpr int ROW_B    = 144;               // 64 halves (128B) + 16B pad
constexpr int TILE_B   = 128 * ROW_B;       // 18432
constexpr int STAGE_B  = 2 * TILE_B;        // 36864 (A | W)
constexpr int SMEM_TOT = 3 * STAGE_B;       // 110592
#define GEMM_THREADS 256

__device__ __forceinline__ void load_stage(
    uint32_t sb_stage, int kb, int tid,
    const __half* __restrict__ A, const __half* __restrict__ W, int bm, int bn)
{
#pragma unroll
    for (int i = 0; i < 8; i++) {
        const int idx = i * 256 + tid;          // 0..2047
        const int t   = idx >> 10;              // 0 = A, 1 = W
        const int row = (idx >> 3) & 127;
        const int ch  = idx & 7;
        const __half* src = (t ? W : A) + (((size_t)((t ? bn : bm) + row)) << 10)
                          + kb * 64 + ch * 8;
        CP_ASYNC16(sb_stage + t * TILE_B + row * ROW_B + ch * 16, src);
    }
}

template <bool OUT_FP16, bool RESID>
__device__ __forceinline__ void gemm_body(
    const __half* __restrict__ A, const __half* __restrict__ W,
    const float* __restrict__ bias, const float* __restrict__ resid,
    float* __restrict__ Cf, __half* __restrict__ Ch, int bm, int bn)
{
    extern __shared__ __align__(128) char smem[];
    const uint32_t sb = smem_u32(smem);
    const int tid  = threadIdx.x;
    const int wid  = tid >> 5;
    const int lane = tid & 31;
    const int wm = (wid >> 1) * 32;   // 0,32,64,96
    const int wn = (wid & 1) * 64;    // 0,64
    const int kstag = (wid >> 2) * 2; // 0 or 2: stagger for SMSP co-residents

    float acc[2][8][4];
#pragma unroll
    for (int i = 0; i < 2; i++)
#pragma unroll
        for (int j = 0; j < 8; j++)
#pragma unroll
            for (int k = 0; k < 4; k++) acc[i][j][k] = 0.0f;

    load_stage(sb + 0 * STAGE_B, 0, tid, A, W, bm, bn); CP_COMMIT();
    load_stage(sb + 1 * STAGE_B, 1, tid, A, W, bm, bn); CP_COMMIT();

    const int sub = lane >> 3;
    const int rr  = lane & 7;
    const int rowsel = (sub & 1) * 8 + rr;
    const int ksel   = (sub >> 1) * 16;

    for (int kb = 0; kb < 16; kb++) {
        CP_WAIT1();
        __syncthreads();
        if (kb + 2 < 16)
            load_stage(sb + ((kb + 2) % 3) * STAGE_B, kb + 2, tid, A, W, bm, bn);
        CP_COMMIT();

        const uint32_t st = sb + (kb % 3) * STAGE_B;
        const uint32_t sA = st;
        const uint32_t sB = st + TILE_B;

#pragma unroll
        for (int kq = 0; kq < 4; kq++) {
            const int kk = (kq + kstag) & 3;
            const int koff = kk * 32 + ksel;
            uint32_t fa[2][4], fb[4][4];
#pragma unroll
            for (int mt = 0; mt < 2; mt++)
                ldsm4(fa[mt], sA + (wm + mt * 16 + rowsel) * ROW_B + koff);
#pragma unroll
            for (int g = 0; g < 4; g++)
                ldsm4(fb[g], sB + (wn + g * 16 + rowsel) * ROW_B + koff);
#pragma unroll
            for (int mt = 0; mt < 2; mt++) {
#pragma unroll
                for (int g = 0; g < 4; g++) {
                    mma_f16(acc[mt][2 * g],     fa[mt], fb[g][0], fb[g][2]);
                    mma_f16(acc[mt][2 * g + 1], fa[mt], fb[g][1], fb[g][3]);
                }
            }
        }
    }

    const int qrow = lane >> 2;
    const int qcol = (lane & 3) * 2;
#pragma unroll
    for (int mt = 0; mt < 2; mt++) {
#pragma unroll
        for (int nt = 0; nt < 8; nt++) {
            const int col = bn + wn + nt * 8 + qcol;
            const float bz0 = __ldg(bias + col);
            const float bz1 = __ldg(bias + col + 1);
#pragma unroll
            for (int h = 0; h < 2; h++) {
                const int row = bm + wm + mt * 16 + h * 8 + qrow;
                float v0 = acc[mt][nt][2 * h + 0] * 0.015625f + bz0;
                float v1 = acc[mt][nt][2 * h + 1] * 0.015625f + bz1;
                const size_t go = ((size_t)row << 10) + col;
                if (RESID) {
                    float2 x2 = *(const float2*)(resid + go);
                    v0 += x2.x; v1 += x2.y;
                }
                if (OUT_FP16) {
                    __half2 hv = __floats2half2_rn(v0, v1);
                    *(uint32_t*)(Ch + go) = *(uint32_t*)&hv;
                } else {
                    float2 o; o.x = v0; o.y = v1;
                    *(float2*)(Cf + go) = o;
                }
            }
        }
    }
}

// value GEMM (1024 tiles) + the two weight-combine GEMMs (128 tiles), one launch.
__global__ __launch_bounds__(GEMM_THREADS, 2)
void gemm_value_combine(
    const __half* __restrict__ xh, const __half* __restrict__ whV,
    const float* __restrict__ bv, __half* __restrict__ vh,
    const __half* __restrict__ whKP, const __half* __restrict__ whKT, __half* __restrict__ whCK,
    const __half* __restrict__ whQP, const __half* __restrict__ whQT, __half* __restrict__ whCQ,
    const float* __restrict__ zerob)
{
    const int by = blockIdx.y;
    const int bn = blockIdx.x * 128;
    if (by < 128) {
        gemm_body<true, false>(xh, whV, bv, nullptr, nullptr, vh, by * 128, bn);
    } else if (by < 136) {
        gemm_body<true, false>(whKP, whKT, zerob, nullptr, nullptr, whCK, (by - 128) * 128, bn);
    } else {
        gemm_body<true, false>(whQP, whQT, zerob, nullptr, nullptr, whCQ, (by - 136) * 128, bn);
    }
}

// kp + qp GEMMs in one launch: grid (8, 128, 2)
__global__ __launch_bounds__(GEMM_THREADS, 2)
void gemm_kq_dual(const __half* __restrict__ xh,
                  const __half* __restrict__ whCK, const float* __restrict__ bkpc, __half* __restrict__ kh,
                  const __half* __restrict__ whCQ, const float* __restrict__ bqpc, __half* __restrict__ qh)
{
    if (blockIdx.z == 0)
        gemm_body<true, false>(xh, whCK, bkpc, nullptr, nullptr, kh, blockIdx.y * 128, blockIdx.x * 128);
    else
        gemm_body<true, false>(xh, whCQ, bqpc, nullptr, nullptr, qh, blockIdx.y * 128, blockIdx.x * 128);
}

// out-projection GEMM with residual, fp32 output
__global__ __launch_bounds__(GEMM_THREADS, 2)
void gemm_out(const __half* __restrict__ A, const __half* __restrict__ W,
              const float* __restrict__ bias, const float* __restrict__ resid,
              float* __restrict__ Cf)
{
    gemm_body<false, true>(A, W, bias, resid, Cf, nullptr, blockIdx.y * 128, blockIdx.x * 128);
}

// ---------------------------------------------------------------------------
// Fused phasor + LayerNorm: 128 blocks (ONE wave) x 512 threads.
// Each block handles TWO chunks: threads 0-255 -> chunk 2b, 256-511 -> 2b+1.
// Groups sync independently via named barriers (bar.sync id,256).
// Per group: 4 d/thread, 8 s-steps batched per reduction round (R14 logic).
// ---------------------------------------------------------------------------
#define LNP_THREADS 512
__global__ __launch_bounds__(LNP_THREADS, 1)
void lnphasor_kernel(const __half* __restrict__ kp16, const __half* __restrict__ qp16,
                     const __half* __restrict__ v16,  const float* __restrict__ ps,
                     const float* __restrict__ lng,   const float* __restrict__ lnb,
                     __half* __restrict__ outh)
{
    __shared__ float sred[2][128];   // per group: [16 values][8 warps]
    __shared__ float smu[2][16];     // per group: s1[0..7], s2[0..7]
    const int tid   = threadIdx.x;
    const int grp   = tid >> 8;      // 0 or 1
    const int gtid  = tid & 255;
    const int warp  = gtid >> 5;     // warp within group: 0..7
    const int lane  = tid & 31;
    const int bar   = grp + 1;       // named barrier id 1 or 2
    const int chunk = blockIdx.x * 2 + grp;
    const int d0 = gtid * 4;

    const float4 ps4 = *(const float4*)(ps + d0);
    const float4 g4  = *(const float4*)(lng + d0);
    const float4 b4  = *(const float4*)(lnb + d0);
    const float psv[4] = {ps4.x, ps4.y, ps4.z, ps4.w};
    const float gv[4]  = {g4.x, g4.y, g4.z, g4.w};
    const float bv[4]  = {b4.x, b4.y, b4.z, b4.w};

    float mr[4] = {0, 0, 0, 0}, mi[4] = {0, 0, 0, 0};
    const size_t base = ((size_t)chunk * CHUNKq << 10) + d0;

    for (int s8 = 0; s8 < CHUNKq / 8; s8++) {
        float r[8][4];
        float s1[8], s2[8];
#pragma unroll
        for (int u = 0; u < 8; u++) {
            const size_t off = base + ((size_t)(s8 * 8 + u) << 10);
            uint2 kpu = *(const uint2*)(kp16 + off);
            uint2 qpu = *(const uint2*)(qp16 + off);
            uint2 vu  = *(const uint2*)(v16 + off);
            float2 kpa = __half22float2(*(__half2*)&kpu.x);
            float2 kpb = __half22float2(*(__half2*)&kpu.y);
            float2 qpa = __half22float2(*(__half2*)&qpu.x);
            float2 qpb = __half22float2(*(__half2*)&qpu.y);
            float2 va  = __half22float2(*(__half2*)&vu.x);
            float2 vb  = __half22float2(*(__half2*)&vu.y);
            const float kpf[4] = {kpa.x, kpa.y, kpb.x, kpb.y};
            const float qpf[4] = {qpa.x, qpa.y, qpb.x, qpb.y};
            const float vf[4]  = {va.x, va.y, vb.x, vb.y};
            float a1 = 0.0f, a2 = 0.0f;
#pragma unroll
            for (int j = 0; j < 4; j++) {
                const float kp = ftanh(kpf[j]) * psv[j];
                const float qp = ftanh(qpf[j]) * psv[j];
                mr[j] = fmaf(vf[j], fcos(kp), mr[j]);
                mi[j] = fmaf(vf[j], fsin(kp), mi[j]);
                r[u][j] = (mr[j] * fcos(qp) + mi[j] * fsin(qp)) * 0.03125f;
                a1 += r[u][j];
                a2 = fmaf(r[u][j], r[u][j], a2);
            }
            s1[u] = a1; s2[u] = a2;
        }
#pragma unroll
        for (int o = 16; o > 0; o >>= 1) {
#pragma unroll
            for (int u = 0; u < 8; u++) {
                s1[u] += __shfl_xor_sync(0xFFFFFFFFu, s1[u], o);
                s2[u] += __shfl_xor_sync(0xFFFFFFFFu, s2[u], o);
            }
        }
        if (lane == 0) {
#pragma unroll
            for (int u = 0; u < 8; u++) {
                sred[grp][u * 8 + warp] = s1[u];
                sred[grp][(8 + u) * 8 + warp] = s2[u];
            }
        }
        BAR_SYNC_256(bar);
        if (warp == 0) {
#pragma unroll
            for (int t = 0; t < 4; t++) {
                float a = sred[grp][t * 32 + lane];
#pragma unroll
                for (int o = 4; o > 0; o >>= 1)
                    a += __shfl_xor_sync(0xFFFFFFFFu, a, o);
                if ((lane & 7) == 0) smu[grp][t * 4 + (lane >> 3)] = a;
            }
        }
        BAR_SYNC_256(bar);
#pragma unroll
        for (int u = 0; u < 8; u++) {
            const float mu   = smu[grp][u] * (1.0f / Dq);
            const float var  = smu[grp][8 + u] * (1.0f / Dq) - mu * mu;
            const float rstd = rsqrtf(var + 1e-5f);
            __half2 h0 = __floats2half2_rn((r[u][0] - mu) * rstd * gv[0] + bv[0],
                                           (r[u][1] - mu) * rstd * gv[1] + bv[1]);
            __half2 h1 = __floats2half2_rn((r[u][2] - mu) * rstd * gv[2] + bv[2],
                                           (r[u][3] - mu) * rstd * gv[3] + bv[3]);
            uint2 p;
            p.x = *(uint32_t*)&h0;
            p.y = *(uint32_t*)&h1;
            const size_t off = base + ((size_t)(s8 * 8 + u) << 10);
            *(uint2*)(outh + off) = p;
        }
        BAR_SYNC_256(bar);
    }
}

// ---------------------------------------------------------------------------
// Launch
// ---------------------------------------------------------------------------
extern "C" void kernel_launch(void* const* d_in, const int* in_sizes, int n_in,
                              void* d_out, int out_size)
{
    (void)in_sizes; (void)n_in; (void)out_size;
    const float* x   = (const float*)d_in[0];
    const float* Wk  = (const float*)d_in[1];
    const float* bk  = (const float*)d_in[2];
    const float* Wv  = (const float*)d_in[3];
    const float* bv  = (const float*)d_in[4];
    const float* Wq  = (const float*)d_in[5];
    const float* bq  = (const float*)d_in[6];
    const float* Wkp = (const float*)d_in[7];
    const float* bkp = (const float*)d_in[8];
    const float* Wqp = (const float*)d_in[9];
    const float* bqp = (const float*)d_in[10];
    const float* ps  = (const float*)d_in[11];
    const float* lng = (const float*)d_in[12];
    const float* lnb = (const float*)d_in[13];
    const float* Wo  = (const float*)d_in[14];
    const float* bo  = (const float*)d_in[15];
    float* out = (float*)d_out;

    float *zero, *bkpc, *bqpc;
    __half *xh, *vh, *kh, *qh, *ah, *wh;
    cudaGetSymbolAddress((void**)&xh, g_xh);
    cudaGetSymbolAddress((void**)&vh, g_vh);
    cudaGetSymbolAddress((void**)&kh, g_kh);
    cudaGetSymbolAddress((void**)&qh, g_qh);
    cudaGetSymbolAddress((void**)&ah, g_ah);
    cudaGetSymbolAddress((void**)&wh, g_wh);
    cudaGetSymbolAddress((void**)&zero, g_zero);
    cudaGetSymbolAddress((void**)&bkpc, g_bkp);
    cudaGetSymbolAddress((void**)&bqpc, g_bqp);

    cudaFuncSetAttribute(gemm_value_combine, cudaFuncAttributeMaxDynamicSharedMemorySize, SMEM_TOT);
    cudaFuncSetAttribute(gemm_kq_dual,       cudaFuncAttributeMaxDynamicSharedMemorySize, SMEM_TOT);
    cudaFuncSetAttribute(gemm_out,           cudaFuncAttributeMaxDynamicSharedMemorySize, SMEM_TOT);

    const size_t WN = (size_t)Dq * Dq;
    __half* whV  = wh + 0 * WN;
    __half* whO  = wh + 1 * WN;
    __half* whKP = wh + 2 * WN;
    __half* whQP = wh + 3 * WN;
    __half* whKT = wh + 4 * WN;
    __half* whQT = wh + 5 * WN;
    __half* whCK = wh + 6 * WN;
    __half* whCQ = wh + 7 * WN;

    // ONE prep launch: x convert + weight converts + transposes + bias matvecs
    prep_kernel<<<dim3(1024, 24), 256>>>(
        x, xh, Wv, Wo, Wkp, Wqp, whV, whO, whKP, whQP,
        Wk, whKT, Wq, whQT, bk, bkp, bkpc, bq, bqp, bqpc);

    const dim3 block(GEMM_THREADS);
    // value GEMM + weight combines, one launch
    gemm_value_combine<<<dim3(8, 144), block, SMEM_TOT>>>(
        xh, whV, bv, vh, whKP, whKT, whCK, whQP, whQT, whCQ, zero);

    // kp + qp GEMMs, one launch
    gemm_kq_dual<<<dim3(8, 128, 2), block, SMEM_TOT>>>(xh, whCK, bkpc, kh, whCQ, bqpc, qh);

    // Fused phasor + layernorm -> ah (fp16); 128 blocks = one wave
    lnphasor_kernel<<<Bq * NCHUNK / 2, LNP_THREADS>>>(kh, qh, vh, ps, lng, lnb, ah);

    // out = x + ln @ Wo + bo
    gemm_out<<<dim3(8, 128), block, SMEM_TOT>>>(ah, whO, bo, x, out);
}